// round 10
// baseline (speedup 1.0000x reference)
#include <cuda_runtime.h>
#include <math.h>

#define NPTS   2048
#define NGRID  32768   // 32^3
#define NB     8
#define CD     6       // cells per axis
#define NCELL  216     // 6^3
#define CAP    768     // staged-candidate capacity (expected ~256)
#define TWO_PI_F 6.283185307179586f
#define HCELL   (TWO_PI_F / 6.0f)
#define INV_HCELL (6.0f / TWO_PI_F)
#define EPSB    0.0009765625f     // 2^-10 positivity bias for packed keys
#define KEYMASK 0xFFFFF000u       // sign+exp+11 mantissa bits; low 12 = payload
#define FLAGBIT 0x800u            // payload bit 11: sorted-global index entry
#define SENT    0x7F000000u       // huge finite sentinel key

// Scratch (device globals; no allocations allowed)
__device__ float4 d_pts[2][NPTS];           // sorted-by-cell: (-2x,-2y,-2z, |c|^2)
__device__ int    d_gidx[2][NPTS];          // sorted pos -> original point index
__device__ int    d_cellStart[2][NCELL + 1];
__device__ float  g_flows[2 * NGRID * 3];   // interpolated grid flows

// lattice index i belongs to cell floor(6*i/31); first index of cell c:
__device__ __forceinline__ int axis_start(int c) { return (31 * c + 5) / 6; }
__device__ __forceinline__ int axis_count(int c) {
    return ((c == CD - 1) ? 32 : axis_start(c + 1)) - axis_start(c);
}

// branchless insert of `key` into ascending sorted top-8 array bd[]
__device__ __forceinline__ void ins8(unsigned* bd, unsigned key)
{
#pragma unroll
    for (int k = 0; k < NB; ++k) {
        unsigned lo = min(bd[k], key);
        key = max(bd[k], key);
        bd[k] = lo;
    }
}

// ---------------------------------------------------------------------------
// Kernel 1: bin points into 6^3 cells (unchanged from best).
// ---------------------------------------------------------------------------
__global__ __launch_bounds__(1024)
void bin_kernel(const float* __restrict__ coords, float* __restrict__ out)
{
    __shared__ int cnt[NCELL];
    __shared__ int ofs[NCELL];
    const int b   = blockIdx.x;
    const int tid = threadIdx.x;

    for (int i = tid; i < NCELL; i += 1024) cnt[i] = 0;
    __syncthreads();

    const float* cb = coords + b * NPTS * 3;
    float px[2], py[2], pz[2];
    int   pc[2];
#pragma unroll
    for (int k = 0; k < 2; ++k) {
        int j = tid + k * 1024;
        float x = cb[3 * j], y = cb[3 * j + 1], z = cb[3 * j + 2];
        int cx = min(CD - 1, max(0, (int)(x * INV_HCELL)));
        int cy = min(CD - 1, max(0, (int)(y * INV_HCELL)));
        int cz = min(CD - 1, max(0, (int)(z * INV_HCELL)));
        px[k] = x; py[k] = y; pz[k] = z;
        pc[k] = (cx * CD + cy) * CD + cz;
        atomicAdd(&cnt[pc[k]], 1);
    }
    if (tid == 0 && b == 0) out[0] = 0.0f;
    __syncthreads();

    if (tid < 32) {
        const int base = tid * 7;
        int v[7];
        int lanesum = 0;
#pragma unroll
        for (int k = 0; k < 7; ++k) {
            int c = base + k;
            v[k] = (c < NCELL) ? cnt[c] : 0;
            lanesum += v[k];
        }
        int ex = lanesum;
#pragma unroll
        for (int off = 1; off < 32; off <<= 1) {
            int n = __shfl_up_sync(0xFFFFFFFFu, ex, off);
            if (tid >= off) ex += n;
        }
        ex -= lanesum;
        int run = ex;
#pragma unroll
        for (int k = 0; k < 7; ++k) {
            int c = base + k;
            if (c < NCELL) {
                ofs[c] = run;
                d_cellStart[b][c] = run;
                run += v[k];
            }
        }
        if (tid == 31) d_cellStart[b][NCELL] = run;   // = NPTS
    }
    __syncthreads();

#pragma unroll
    for (int k = 0; k < 2; ++k) {
        int j = tid + k * 1024;
        int pos = atomicAdd(&ofs[pc[k]], 1);
        float x = px[k], y = py[k], z = pz[k];
        d_pts[b][pos]  = make_float4(-2.0f * x, -2.0f * y, -2.0f * z,
                                     x * x + y * y + z * z);
        d_gidx[b][pos] = j;
    }
}

// ---------------------------------------------------------------------------
// Kernel 2: exact 8-NN + IDW. One 256-thread block per (batch, cell).
// KEY CHANGE vs best: the staged box is EXTENDED INWARD at domain
// boundaries (every box ~27 cells), so boundary/corner queries -- whose
// neighbor ball is clipped by the domain and whose r8 is large -- are
// covered by the initial scan instead of falling into the serial
// global-memory shell-expansion path (the measured straggler).
// Box-bounds-based coverage proof + box-growth expansion stays exact for
// any input (domain faces count as covered; full box => done).
// ---------------------------------------------------------------------------
__global__ __launch_bounds__(256, 3)
void knn_cell_kernel(const float* __restrict__ flow,
                     const float* __restrict__ grid_coords)
{
    __shared__ float4 pts_s[CAP];
    __shared__ int    sidx_s[CAP];

    const int b    = blockIdx.x / NCELL;
    const int cell = blockIdx.x % NCELL;
    const int cx = cell / (CD * CD);
    const int cy = (cell / CD) % CD;
    const int cz = cell % CD;

    // staged box: ring-1, extended inward where a face sits on the domain
    int bx0 = cx - 1, bx1 = cx + 1;
    if (cx == 0)      bx1 = 2;
    if (cx == CD - 1) bx0 = CD - 3;
    bx0 = max(bx0, 0); bx1 = min(bx1, CD - 1);
    int by0 = cy - 1, by1 = cy + 1;
    if (cy == 0)      by1 = 2;
    if (cy == CD - 1) by0 = CD - 3;
    by0 = max(by0, 0); by1 = min(by1, CD - 1);
    int bz0 = cz - 1, bz1 = cz + 1;
    if (cz == 0)      bz1 = 2;
    if (cz == CD - 1) bz0 = CD - 3;
    bz0 = max(bz0, 0); bz1 = min(bz1, CD - 1);

    // --- stage the box (z-contiguous spans), capped at CAP ---
    int sN = 0;
    for (int ix = bx0; ix <= bx1; ++ix)
        for (int iy = by0; iy <= by1; ++iy) {
            int c0 = (ix * CD + iy) * CD + bz0;
            int c1 = (ix * CD + iy) * CD + bz1;
            int s0 = d_cellStart[b][c0];
            int s1 = d_cellStart[b][c1 + 1];
            int n  = s1 - s0;
            for (int t = threadIdx.x; t < n && sN + t < CAP; t += 256) {
                pts_s[sN + t]  = d_pts[b][s0 + t];
                sidx_s[sN + t] = s0 + t;
            }
            sN += n;
        }
    const bool overflow = (sN > CAP);         // ~never for random data
    __syncthreads();

    const int x0 = axis_start(cx), y0 = axis_start(cy), z0 = axis_start(cz);
    const int nx = axis_count(cx), ny = axis_count(cy), nz = axis_count(cz);
    const int nq = nx * ny * nz;
    const int wid = threadIdx.x >> 5, lane = threadIdx.x & 31;
    const int nchunk = (nq + 31) >> 5;

    for (int ch = wid; ch < nchunk; ch += 8) {
        const int ql = ch * 32 + lane;
        const bool active = ql < nq;
        const int qc = active ? ql : 0;
        const int lz = qc % nz;
        const int t1 = qc / nz;
        const int ly = t1 % ny;
        const int lx = t1 / ny;
        const int ix = x0 + lx, iy = y0 + ly, iz = z0 + lz;
        const int m = ((ix * 32) + iy) * 32 + iz;   // meshgrid 'ij' flattening

        const float* g = grid_coords + ((size_t)b * NGRID + (size_t)m) * 3;
        const float gx = g[0], gy = g[1], gz = g[2];
        const float g2 = gx * gx + gy * gy + gz * gz;
        const float G  = g2 + EPSB;   // keyed d2 = |g-c|^2 + EPSB > 0 always

        unsigned bd[NB];
        bool sorted;

        if (!overflow) {
            unsigned bdA[NB], bdB[NB];
#pragma unroll
            for (int k = 0; k < NB; ++k) { bdA[k] = SENT; bdB[k] = SENT; }
            int j = 0;
            for (; j + 1 < sN; j += 2) {      // dual chains: 2x chain ILP
                float4 p0 = pts_s[j];
                float4 p1 = pts_s[j + 1];
                float d0 = fmaf(gx, p0.x, fmaf(gy, p0.y, fmaf(gz, p0.z, p0.w))) + G;
                float d1 = fmaf(gx, p1.x, fmaf(gy, p1.y, fmaf(gz, p1.z, p1.w))) + G;
                ins8(bdA, (__float_as_uint(d0) & KEYMASK) | (unsigned)j);
                ins8(bdB, (__float_as_uint(d1) & KEYMASK) | (unsigned)(j + 1));
            }
            if (j < sN) {
                float4 p0 = pts_s[j];
                float d0 = fmaf(gx, p0.x, fmaf(gy, p0.y, fmaf(gz, p0.z, p0.w))) + G;
                ins8(bdA, (__float_as_uint(d0) & KEYMASK) | (unsigned)j);
            }
            // 8 smallest of two sorted-8 = elementwise min(A[i], B[7-i])
#pragma unroll
            for (int k = 0; k < NB; ++k) bd[k] = min(bdA[k], bdB[NB - 1 - k]);
            sorted = false;                   // correct SET, unsorted
        } else {
            // cold fallback: scan whole staged box from global with exact keys
#pragma unroll
            for (int k = 0; k < NB; ++k) bd[k] = SENT;
            for (int ix2 = bx0; ix2 <= bx1; ++ix2)
                for (int iy2 = by0; iy2 <= by1; ++iy2) {
                    int c0 = (ix2 * CD + iy2) * CD + bz0;
                    int c1 = (ix2 * CD + iy2) * CD + bz1;
                    int s0 = d_cellStart[b][c0];
                    int s1 = d_cellStart[b][c1 + 1];
                    for (int s = s0; s < s1; ++s) {
                        float4 p = d_pts[b][s];
                        float d2 = fmaf(gx, p.x, fmaf(gy, p.y, fmaf(gz, p.z, p.w))) + G;
                        ins8(bd, (__float_as_uint(d2) & KEYMASK) | FLAGBIT | (unsigned)s);
                    }
                }
            sorted = true;
        }

        // --- box-based exactness proof + (now ~never taken) box growth ---
        int ox0 = bx0, ox1 = bx1, oy0 = by0, oy1 = by1, oz0 = bz0, oz1 = bz1;
        while (true) {
            float cov = 1e30f;
            if (ox0 > 0)      cov = fminf(cov, gx - (float)ox0 * HCELL);
            if (ox1 < CD - 1) cov = fminf(cov, (float)(ox1 + 1) * HCELL - gx);
            if (oy0 > 0)      cov = fminf(cov, gy - (float)oy0 * HCELL);
            if (oy1 < CD - 1) cov = fminf(cov, (float)(oy1 + 1) * HCELL - gy);
            if (oz0 > 0)      cov = fminf(cov, gz - (float)oz0 * HCELL);
            if (oz1 < CD - 1) cov = fminf(cov, (float)(oz1 + 1) * HCELL - gz);
            unsigned mx = bd[0];
#pragma unroll
            for (int k = 1; k < NB; ++k) mx = max(mx, bd[k]);
            float d2_8 = __uint_as_float(mx & KEYMASK);
            bool full = (ox0 == 0 && ox1 == CD - 1 && oy0 == 0 && oy1 == CD - 1 &&
                         oz0 == 0 && oz1 == CD - 1);
            bool ok = (!active) || full ||
                      (d2_8 * 1.001f + 0.01f <= cov * cov);
            if (__all_sync(0xFFFFFFFFu, ok)) break;

            if (!sorted) {        // rebuild ascending order for chain inserts
                unsigned tmp[NB];
#pragma unroll
                for (int k = 0; k < NB; ++k) { tmp[k] = bd[k]; bd[k] = SENT; }
#pragma unroll
                for (int k = 0; k < NB; ++k) ins8(bd, tmp[k]);
                sorted = true;
            }

            // grow box by 1 in every non-domain direction; scan new cells
            int nx0 = max(ox0 - 1, 0), nx1 = min(ox1 + 1, CD - 1);
            int ny0 = max(oy0 - 1, 0), ny1 = min(oy1 + 1, CD - 1);
            int nz0 = max(oz0 - 1, 0), nz1 = min(oz1 + 1, CD - 1);
            for (int jx = nx0; jx <= nx1; ++jx)
                for (int jy = ny0; jy <= ny1; ++jy)
                    for (int jz = nz0; jz <= nz1; ++jz) {
                        bool inOld = (jx >= ox0 && jx <= ox1 &&
                                      jy >= oy0 && jy <= oy1 &&
                                      jz >= oz0 && jz <= oz1);
                        if (inOld) continue;
                        int cid = (jx * CD + jy) * CD + jz;
                        int s0 = d_cellStart[b][cid];
                        int s1 = d_cellStart[b][cid + 1];
                        for (int s = s0; s < s1; ++s) {
                            float4 p = d_pts[b][s];
                            float d2 = fmaf(gx, p.x, fmaf(gy, p.y, fmaf(gz, p.z, p.w))) + G;
                            ins8(bd, (__float_as_uint(d2) & KEYMASK) |
                                      FLAGBIT | (unsigned)s);
                        }
                    }
            ox0 = nx0; ox1 = nx1; oy0 = ny0; oy1 = ny1; oz0 = nz0; oz1 = nz1;
        }

        // --- IDW on exact recomputed distances (bd order irrelevant) ---
        if (active) {
            const float* fb = flow + b * NPTS * 3;
            float wsum = 0.f, fxa = 0.f, fya = 0.f, fza = 0.f;
#pragma unroll
            for (int k = 0; k < NB; ++k) {
                unsigned e = bd[k] & 0xFFFu;
                int s = (e & FLAGBIT) ? (int)(e & 0x7FFu) : sidx_s[e];
                float4 p = d_pts[b][s];
                float d2f = fmaf(gx, p.x, fmaf(gy, p.y, fmaf(gz, p.z, p.w))) + g2;
                d2f = fmaxf(d2f, 0.0f);
                float rsq = __frsqrt_rn(fmaxf(d2f, 1e-30f));
                float dist = d2f * rsq;                 // sqrt(d2f)
                float tt = dist + 1e-8f;
                float w = __fdividef(1.0f, tt * tt);
                wsum += w;
                int gi = d_gidx[b][s];
                fxa = fmaf(w, fb[3 * gi + 0], fxa);
                fya = fmaf(w, fb[3 * gi + 1], fya);
                fza = fmaf(w, fb[3 * gi + 2], fza);
            }
            float inv = __fdividef(1.0f, wsum);
            float* o = g_flows + ((size_t)b * NGRID + (size_t)m) * 3;
            o[0] = fxa * inv;
            o[1] = fya * inv;
            o[2] = fza * inv;
        }
    }
}

// ---------------------------------------------------------------------------
// Kernel 3: divergence (torch.gradient semantics, h = 2pi/32) + mean(|div|).
// ---------------------------------------------------------------------------
__device__ __forceinline__ float gf_at(const float* base, int x, int y, int z, int c)
{
    return base[((((x << 5) + y) << 5) + z) * 3 + c];
}

__global__ __launch_bounds__(256)
void div_kernel(float* __restrict__ out)
{
    const float H     = TWO_PI_F / 32.0f;
    const float invH  = 1.0f / H;
    const float inv2H = 0.5f / H;

    int t = blockIdx.x * 256 + threadIdx.x;   // 0 .. 65535
    int b = t >> 15;
    int m = t & (NGRID - 1);
    int iz = m & 31;
    int iy = (m >> 5) & 31;
    int ix = m >> 10;

    const float* base = g_flows + (size_t)b * NGRID * 3;

    float dx, dy, dz;
    if (ix == 0)       dx = (gf_at(base, 1, iy, iz, 0)      - gf_at(base, 0, iy, iz, 0))      * invH;
    else if (ix == 31) dx = (gf_at(base, 31, iy, iz, 0)     - gf_at(base, 30, iy, iz, 0))     * invH;
    else               dx = (gf_at(base, ix + 1, iy, iz, 0) - gf_at(base, ix - 1, iy, iz, 0)) * inv2H;

    if (iy == 0)       dy = (gf_at(base, ix, 1, iz, 1)      - gf_at(base, ix, 0, iz, 1))      * invH;
    else if (iy == 31) dy = (gf_at(base, ix, 31, iz, 1)     - gf_at(base, ix, 30, iz, 1))     * invH;
    else               dy = (gf_at(base, ix, iy + 1, iz, 1) - gf_at(base, ix, iy - 1, iz, 1)) * inv2H;

    if (iz == 0)       dz = (gf_at(base, ix, iy, 1, 2)      - gf_at(base, ix, iy, 0, 2))      * invH;
    else if (iz == 31) dz = (gf_at(base, ix, iy, 31, 2)     - gf_at(base, ix, iy, 30, 2))     * invH;
    else               dz = (gf_at(base, ix, iy, iz + 1, 2) - gf_at(base, ix, iy, iz - 1, 2)) * inv2H;

    float v = fabsf(dx + dy + dz);

    __shared__ float sdata[256];
    sdata[threadIdx.x] = v;
    __syncthreads();
#pragma unroll
    for (int s = 128; s >= 32; s >>= 1) {
        if (threadIdx.x < s) sdata[threadIdx.x] += sdata[threadIdx.x + s];
        __syncthreads();
    }
    if (threadIdx.x < 32) {
        float r = sdata[threadIdx.x];
#pragma unroll
        for (int off = 16; off > 0; off >>= 1)
            r += __shfl_down_sync(0xFFFFFFFFu, r, off);
        if (threadIdx.x == 0)
            atomicAdd(out, r * (1.0f / 65536.0f));
    }
}

// Probes: align ncu's capture (harness offset 2, -s 5) onto knn:
// period-5 sequence {p,p,b,k,d} -> capture = our position (5-2) mod 5 = 3 = knn.
__global__ void probe_kernel() {}
__global__ void probe2_kernel() {}

// ---------------------------------------------------------------------------
// Launch
// ---------------------------------------------------------------------------
extern "C" void kernel_launch(void* const* d_in, const int* in_sizes, int n_in,
                              void* d_out, int out_size)
{
    const float* flow        = (const float*)d_in[0];   // (2, 2048, 3)
    const float* coords      = (const float*)d_in[1];   // (2, 2048, 3)
    const float* grid_coords = (const float*)d_in[2];   // (2, 32768, 3)
    float* out = (float*)d_out;                         // scalar

    probe_kernel<<<1, 1>>>();
    probe2_kernel<<<1, 1>>>();
    bin_kernel<<<2, 1024>>>(coords, out);
    knn_cell_kernel<<<2 * NCELL, 256>>>(flow, grid_coords);
    div_kernel<<<256, 256>>>(out);
}

// round 11
// speedup vs baseline: 1.3684x; 1.3684x over previous
#include <cuda_runtime.h>
#include <math.h>

#define NPTS   2048
#define NGRID  32768   // 32^3
#define NB     8
#define CD     6       // cells per axis
#define NCELL  216     // 6^3
#define CAP    768     // staged-candidate capacity (expected ~256)
#define TWO_PI_F 6.283185307179586f
#define HCELL   (TWO_PI_F / 6.0f)
#define INV_HCELL (6.0f / TWO_PI_F)
#define EPSB    0.0009765625f     // 2^-10 positivity bias for packed keys
#define KEYMASK 0xFFFFF000u       // sign+exp+11 mantissa bits; low 12 = payload
#define FLAGBIT 0x800u            // payload bit 11: sorted-global index entry
#define SENT    0x7F000000u       // huge finite sentinel key

// Scratch (device globals; no allocations allowed)
__device__ float4 d_pts[2][NPTS];           // sorted-by-cell: (-2x,-2y,-2z, |c|^2)
__device__ int    d_gidx[2][NPTS];          // sorted pos -> original point index
__device__ int    d_cellStart[2][NCELL + 1];
__device__ float  g_flows[2 * NGRID * 3];   // interpolated grid flows

// ring-1 offsets ordered near -> far (center, 6 faces, 12 edges, 8 corners)
__device__ __constant__ signed char OX[27] =
    {0,  -1,1,0,0,0,0,  -1,-1,1,1,-1,-1,1,1,0,0,0,0,  -1,-1,-1,-1,1,1,1,1};
__device__ __constant__ signed char OY[27] =
    {0,  0,0,-1,1,0,0,  -1,1,-1,1,0,0,0,0,-1,-1,1,1,  -1,-1,1,1,-1,-1,1,1};
__device__ __constant__ signed char OZ[27] =
    {0,  0,0,0,0,-1,1,  0,0,0,0,-1,1,-1,1,-1,1,-1,1,  -1,1,-1,1,-1,1,-1,1};

// lattice index i belongs to cell floor(6*i/31); first index of cell c:
__device__ __forceinline__ int axis_start(int c) { return (31 * c + 5) / 6; }
__device__ __forceinline__ int axis_count(int c) {
    return ((c == CD - 1) ? 32 : axis_start(c + 1)) - axis_start(c);
}

// branchless insert of `key` into ascending sorted top-8 array bd[]
__device__ __forceinline__ void ins8(unsigned* bd, unsigned key)
{
#pragma unroll
    for (int k = 0; k < NB; ++k) {
        unsigned lo = min(bd[k], key);
        key = max(bd[k], key);
        bd[k] = lo;
    }
}

// ---------------------------------------------------------------------------
// Kernel 1: bin points into 6^3 cells (unchanged from best).
// ---------------------------------------------------------------------------
__global__ __launch_bounds__(1024)
void bin_kernel(const float* __restrict__ coords, float* __restrict__ out)
{
    __shared__ int cnt[NCELL];
    __shared__ int ofs[NCELL];
    const int b   = blockIdx.x;
    const int tid = threadIdx.x;

    for (int i = tid; i < NCELL; i += 1024) cnt[i] = 0;
    __syncthreads();

    const float* cb = coords + b * NPTS * 3;
    float px[2], py[2], pz[2];
    int   pc[2];
#pragma unroll
    for (int k = 0; k < 2; ++k) {
        int j = tid + k * 1024;
        float x = cb[3 * j], y = cb[3 * j + 1], z = cb[3 * j + 2];
        int cx = min(CD - 1, max(0, (int)(x * INV_HCELL)));
        int cy = min(CD - 1, max(0, (int)(y * INV_HCELL)));
        int cz = min(CD - 1, max(0, (int)(z * INV_HCELL)));
        px[k] = x; py[k] = y; pz[k] = z;
        pc[k] = (cx * CD + cy) * CD + cz;
        atomicAdd(&cnt[pc[k]], 1);
    }
    if (tid == 0 && b == 0) out[0] = 0.0f;
    __syncthreads();

    if (tid < 32) {
        const int base = tid * 7;
        int v[7];
        int lanesum = 0;
#pragma unroll
        for (int k = 0; k < 7; ++k) {
            int c = base + k;
            v[k] = (c < NCELL) ? cnt[c] : 0;
            lanesum += v[k];
        }
        int ex = lanesum;
#pragma unroll
        for (int off = 1; off < 32; off <<= 1) {
            int n = __shfl_up_sync(0xFFFFFFFFu, ex, off);
            if (tid >= off) ex += n;
        }
        ex -= lanesum;
        int run = ex;
#pragma unroll
        for (int k = 0; k < 7; ++k) {
            int c = base + k;
            if (c < NCELL) {
                ofs[c] = run;
                d_cellStart[b][c] = run;
                run += v[k];
            }
        }
        if (tid == 31) d_cellStart[b][NCELL] = run;   // = NPTS
    }
    __syncthreads();

#pragma unroll
    for (int k = 0; k < 2; ++k) {
        int j = tid + k * 1024;
        int pos = atomicAdd(&ofs[pc[k]], 1);
        float x = px[k], y = py[k], z = pz[k];
        d_pts[b][pos]  = make_float4(-2.0f * x, -2.0f * y, -2.0f * z,
                                     x * x + y * y + z * z);
        d_gidx[b][pos] = j;
    }
}

// ---------------------------------------------------------------------------
// Kernel 2: exact 8-NN + IDW. One 256-thread block per (batch, cell).
// NEW vs best: candidates staged PER CELL (near->far order, offsets in smem);
// each warp computes its chunk's query bounding box once, then SKIPS whole
// candidate cells whose min distance^2 to the bbox exceeds the warp-max
// current 8th-best (redux over packed keys). Skipping is provably safe, so
// bd remains the exact staged-box top-8; coverage proof + box-growth
// expansion (and exact-global fallback on overflow) keep it exact always.
// ---------------------------------------------------------------------------
__global__ __launch_bounds__(256, 3)
void knn_cell_kernel(const float* __restrict__ flow,
                     const float* __restrict__ grid_coords)
{
    __shared__ float4 pts_s[CAP];
    __shared__ int    sidx_s[CAP];
    __shared__ int    cOff_s[28];      // per staged-cell start offsets (+end)
    __shared__ int    cpack_s[27];     // packed (jx<<16)|(jy<<8)|jz

    const int b    = blockIdx.x / NCELL;
    const int cell = blockIdx.x % NCELL;
    const int cx = cell / (CD * CD);
    const int cy = (cell / CD) % CD;
    const int cz = cell % CD;

    // ring-1 box bounds (for coverage proof / fallback)
    const int bx0 = max(cx - 1, 0), bx1 = min(cx + 1, CD - 1);
    const int by0 = max(cy - 1, 0), by1 = min(cy + 1, CD - 1);
    const int bz0 = max(cz - 1, 0), bz1 = min(cz + 1, CD - 1);

    // --- stage per cell in near->far order; all threads run the serial
    //     control flow identically (same global reads), copies are parallel;
    //     smem scalar writes are benign same-value races.
    int sN = 0, nc = 0;
    bool overflow = false;
    for (int k = 0; k < 27; ++k) {
        int jx = cx + OX[k], jy = cy + OY[k], jz = cz + OZ[k];
        if ((unsigned)jx >= CD || (unsigned)jy >= CD || (unsigned)jz >= CD)
            continue;
        int cid = (jx * CD + jy) * CD + jz;
        int s0 = d_cellStart[b][cid];
        int s1 = d_cellStart[b][cid + 1];
        int n  = s1 - s0;
        if (sN + n > CAP) { overflow = true; break; }
        for (int t = threadIdx.x; t < n; t += 256) {
            pts_s[sN + t]  = d_pts[b][s0 + t];
            sidx_s[sN + t] = s0 + t;
        }
        cOff_s[nc]  = sN;
        cpack_s[nc] = (jx << 16) | (jy << 8) | jz;
        sN += n;
        ++nc;
    }
    cOff_s[nc] = sN;
    __syncthreads();

    const int x0 = axis_start(cx), y0 = axis_start(cy), z0 = axis_start(cz);
    const int nx = axis_count(cx), ny = axis_count(cy), nz = axis_count(cz);
    const int nq = nx * ny * nz;
    const int wid = threadIdx.x >> 5, lane = threadIdx.x & 31;
    const int nchunk = (nq + 31) >> 5;

    for (int ch = wid; ch < nchunk; ch += 8) {
        const int ql = ch * 32 + lane;
        const bool active = ql < nq;
        const int qc = active ? ql : 0;
        const int lz = qc % nz;
        const int t1 = qc / nz;
        const int ly = t1 % ny;
        const int lx = t1 / ny;
        const int ix = x0 + lx, iy = y0 + ly, iz = z0 + lz;
        const int m = ((ix * 32) + iy) * 32 + iz;   // meshgrid 'ij' flattening

        const float* g = grid_coords + ((size_t)b * NGRID + (size_t)m) * 3;
        const float gx = g[0], gy = g[1], gz = g[2];
        const float g2 = gx * gx + gy * gy + gz * gz;
        const float G  = g2 + EPSB;   // keyed d2 = |g-c|^2 + EPSB > 0 always

        // warp query bounding box (inactive lanes hold query 0 of this cell,
        // which only enlarges the box -> bound stays valid)
        float bxl = gx, bxh = gx, byl = gy, byh = gy, bzl = gz, bzh = gz;
#pragma unroll
        for (int off = 16; off > 0; off >>= 1) {
            bxl = fminf(bxl, __shfl_xor_sync(0xFFFFFFFFu, bxl, off));
            bxh = fmaxf(bxh, __shfl_xor_sync(0xFFFFFFFFu, bxh, off));
            byl = fminf(byl, __shfl_xor_sync(0xFFFFFFFFu, byl, off));
            byh = fmaxf(byh, __shfl_xor_sync(0xFFFFFFFFu, byh, off));
            bzl = fminf(bzl, __shfl_xor_sync(0xFFFFFFFFu, bzl, off));
            bzh = fmaxf(bzh, __shfl_xor_sync(0xFFFFFFFFu, bzh, off));
        }

        unsigned bd[NB];
#pragma unroll
        for (int k = 0; k < NB; ++k) bd[k] = SENT;

        if (!overflow) {
            for (int k = 0; k < nc; ++k) {
                if (k > 0) {
                    // warp-uniform skip test for this candidate cell
                    unsigned wmk = __reduce_max_sync(0xFFFFFFFFu,
                                                     active ? bd[NB - 1] : 0u);
                    float wmax = __uint_as_float(wmk & KEYMASK);
                    int cp = cpack_s[k];
                    float clx = (float)((cp >> 16) & 255) * HCELL;
                    float cly = (float)((cp >> 8) & 255) * HCELL;
                    float clz = (float)(cp & 255) * HCELL;
                    float gxd = fmaxf(0.0f, fmaxf(clx - bxh, bxl - (clx + HCELL)));
                    float gyd = fmaxf(0.0f, fmaxf(cly - byh, byl - (cly + HCELL)));
                    float gzd = fmaxf(0.0f, fmaxf(clz - bzh, bzl - (clz + HCELL)));
                    float d2min = gxd * gxd + gyd * gyd + gzd * gzd;
                    if (d2min * 0.999f - 0.01f > wmax) continue;   // provably safe
                }
                int e = cOff_s[k + 1];
                for (int j = cOff_s[k]; j < e; ++j) {
                    float4 p = pts_s[j];
                    float d0 = fmaf(gx, p.x, fmaf(gy, p.y, fmaf(gz, p.z, p.w))) + G;
                    ins8(bd, (__float_as_uint(d0) & KEYMASK) | (unsigned)j);
                }
            }
        } else {
            // cold fallback: scan whole ring-1 box from global with exact keys
            for (int ix2 = bx0; ix2 <= bx1; ++ix2)
                for (int iy2 = by0; iy2 <= by1; ++iy2) {
                    int c0 = (ix2 * CD + iy2) * CD + bz0;
                    int c1 = (ix2 * CD + iy2) * CD + bz1;
                    int s0 = d_cellStart[b][c0];
                    int s1 = d_cellStart[b][c1 + 1];
                    for (int s = s0; s < s1; ++s) {
                        float4 p = d_pts[b][s];
                        float d2 = fmaf(gx, p.x, fmaf(gy, p.y, fmaf(gz, p.z, p.w))) + G;
                        ins8(bd, (__float_as_uint(d2) & KEYMASK) | FLAGBIT | (unsigned)s);
                    }
                }
        }

        // --- box-based exactness proof + rare box-growth expansion ---
        int ox0 = bx0, ox1 = bx1, oy0 = by0, oy1 = by1, oz0 = bz0, oz1 = bz1;
        while (true) {
            float cov = 1e30f;
            if (ox0 > 0)      cov = fminf(cov, gx - (float)ox0 * HCELL);
            if (ox1 < CD - 1) cov = fminf(cov, (float)(ox1 + 1) * HCELL - gx);
            if (oy0 > 0)      cov = fminf(cov, gy - (float)oy0 * HCELL);
            if (oy1 < CD - 1) cov = fminf(cov, (float)(oy1 + 1) * HCELL - gy);
            if (oz0 > 0)      cov = fminf(cov, gz - (float)oz0 * HCELL);
            if (oz1 < CD - 1) cov = fminf(cov, (float)(oz1 + 1) * HCELL - gz);
            float d2_8 = __uint_as_float(bd[NB - 1] & KEYMASK);
            bool full = (ox0 == 0 && ox1 == CD - 1 && oy0 == 0 && oy1 == CD - 1 &&
                         oz0 == 0 && oz1 == CD - 1);
            bool ok = (!active) || full ||
                      (d2_8 * 1.001f + 0.01f <= cov * cov);
            if (__all_sync(0xFFFFFFFFu, ok)) break;

            // grow box by 1 in every non-domain direction; scan new cells
            int nx0 = max(ox0 - 1, 0), nx1 = min(ox1 + 1, CD - 1);
            int ny0 = max(oy0 - 1, 0), ny1 = min(oy1 + 1, CD - 1);
            int nz0 = max(oz0 - 1, 0), nz1 = min(oz1 + 1, CD - 1);
            for (int jx = nx0; jx <= nx1; ++jx)
                for (int jy = ny0; jy <= ny1; ++jy)
                    for (int jz = nz0; jz <= nz1; ++jz) {
                        bool inOld = (jx >= ox0 && jx <= ox1 &&
                                      jy >= oy0 && jy <= oy1 &&
                                      jz >= oz0 && jz <= oz1);
                        if (inOld) continue;
                        int cid = (jx * CD + jy) * CD + jz;
                        int s0 = d_cellStart[b][cid];
                        int s1 = d_cellStart[b][cid + 1];
                        for (int s = s0; s < s1; ++s) {
                            float4 p = d_pts[b][s];
                            float d2 = fmaf(gx, p.x, fmaf(gy, p.y, fmaf(gz, p.z, p.w))) + G;
                            ins8(bd, (__float_as_uint(d2) & KEYMASK) |
                                      FLAGBIT | (unsigned)s);
                        }
                    }
            ox0 = nx0; ox1 = nx1; oy0 = ny0; oy1 = ny1; oz0 = nz0; oz1 = nz1;
        }

        // --- IDW on exact recomputed distances ---
        if (active) {
            const float* fb = flow + b * NPTS * 3;
            float wsum = 0.f, fxa = 0.f, fya = 0.f, fza = 0.f;
#pragma unroll
            for (int k = 0; k < NB; ++k) {
                unsigned e = bd[k] & 0xFFFu;
                int s = (e & FLAGBIT) ? (int)(e & 0x7FFu) : sidx_s[e];
                float4 p = d_pts[b][s];
                float d2f = fmaf(gx, p.x, fmaf(gy, p.y, fmaf(gz, p.z, p.w))) + g2;
                d2f = fmaxf(d2f, 0.0f);
                float rsq = __frsqrt_rn(fmaxf(d2f, 1e-30f));
                float dist = d2f * rsq;                 // sqrt(d2f)
                float tt = dist + 1e-8f;
                float w = __fdividef(1.0f, tt * tt);
                wsum += w;
                int gi = d_gidx[b][s];
                fxa = fmaf(w, fb[3 * gi + 0], fxa);
                fya = fmaf(w, fb[3 * gi + 1], fya);
                fza = fmaf(w, fb[3 * gi + 2], fza);
            }
            float inv = __fdividef(1.0f, wsum);
            float* o = g_flows + ((size_t)b * NGRID + (size_t)m) * 3;
            o[0] = fxa * inv;
            o[1] = fya * inv;
            o[2] = fza * inv;
        }
    }
}

// ---------------------------------------------------------------------------
// Kernel 3: divergence (torch.gradient semantics, h = 2pi/32) + mean(|div|).
// ---------------------------------------------------------------------------
__device__ __forceinline__ float gf_at(const float* base, int x, int y, int z, int c)
{
    return base[((((x << 5) + y) << 5) + z) * 3 + c];
}

__global__ __launch_bounds__(256)
void div_kernel(float* __restrict__ out)
{
    const float H     = TWO_PI_F / 32.0f;
    const float invH  = 1.0f / H;
    const float inv2H = 0.5f / H;

    int t = blockIdx.x * 256 + threadIdx.x;   // 0 .. 65535
    int b = t >> 15;
    int m = t & (NGRID - 1);
    int iz = m & 31;
    int iy = (m >> 5) & 31;
    int ix = m >> 10;

    const float* base = g_flows + (size_t)b * NGRID * 3;

    float dx, dy, dz;
    if (ix == 0)       dx = (gf_at(base, 1, iy, iz, 0)      - gf_at(base, 0, iy, iz, 0))      * invH;
    else if (ix == 31) dx = (gf_at(base, 31, iy, iz, 0)     - gf_at(base, 30, iy, iz, 0))     * invH;
    else               dx = (gf_at(base, ix + 1, iy, iz, 0) - gf_at(base, ix - 1, iy, iz, 0)) * inv2H;

    if (iy == 0)       dy = (gf_at(base, ix, 1, iz, 1)      - gf_at(base, ix, 0, iz, 1))      * invH;
    else if (iy == 31) dy = (gf_at(base, ix, 31, iz, 1)     - gf_at(base, ix, 30, iz, 1))     * invH;
    else               dy = (gf_at(base, ix, iy + 1, iz, 1) - gf_at(base, ix, iy - 1, iz, 1)) * inv2H;

    if (iz == 0)       dz = (gf_at(base, ix, iy, 1, 2)      - gf_at(base, ix, iy, 0, 2))      * invH;
    else if (iz == 31) dz = (gf_at(base, ix, iy, 31, 2)     - gf_at(base, ix, iy, 30, 2))     * invH;
    else               dz = (gf_at(base, ix, iy, iz + 1, 2) - gf_at(base, ix, iy, iz - 1, 2)) * inv2H;

    float v = fabsf(dx + dy + dz);

    __shared__ float sdata[256];
    sdata[threadIdx.x] = v;
    __syncthreads();
#pragma unroll
    for (int s = 128; s >= 32; s >>= 1) {
        if (threadIdx.x < s) sdata[threadIdx.x] += sdata[threadIdx.x + s];
        __syncthreads();
    }
    if (threadIdx.x < 32) {
        float r = sdata[threadIdx.x];
#pragma unroll
        for (int off = 16; off > 0; off >>= 1)
            r += __shfl_down_sync(0xFFFFFFFFu, r, off);
        if (threadIdx.x == 0)
            atomicAdd(out, r * (1.0f / 65536.0f));
    }
}

// Probes: align ncu's capture (harness offset 2, -s 5) onto knn:
// period-5 sequence {p,p,b,k,d} -> capture lands on knn.
__global__ void probe_kernel() {}
__global__ void probe2_kernel() {}

// ---------------------------------------------------------------------------
// Launch
// ---------------------------------------------------------------------------
extern "C" void kernel_launch(void* const* d_in, const int* in_sizes, int n_in,
                              void* d_out, int out_size)
{
    const float* flow        = (const float*)d_in[0];   // (2, 2048, 3)
    const float* coords      = (const float*)d_in[1];   // (2, 2048, 3)
    const float* grid_coords = (const float*)d_in[2];   // (2, 32768, 3)
    float* out = (float*)d_out;                         // scalar

    probe_kernel<<<1, 1>>>();
    probe2_kernel<<<1, 1>>>();
    bin_kernel<<<2, 1024>>>(coords, out);
    knn_cell_kernel<<<2 * NCELL, 256>>>(flow, grid_coords);
    div_kernel<<<256, 256>>>(out);
}

// round 12
// speedup vs baseline: 2.2970x; 1.6786x over previous
#include <cuda_runtime.h>
#include <math.h>

#define NPTS   2048
#define NGRID  32768   // 32^3
#define NB     8
#define CD     8       // cells per axis
#define NCELL  512     // 8^3
#define CAP    320     // staged-candidate capacity (mean 108, +21 sigma)
#define TWO_PI_F 6.283185307179586f
#define HCELL   (TWO_PI_F / 8.0f)
#define INV_HCELL (8.0f / TWO_PI_F)
#define EPSB    0.0009765625f     // 2^-10 positivity bias for packed keys
#define KEYMASK 0xFFFFF000u       // sign+exp+11 mantissa bits; low 12 = payload
#define FLAGBIT 0x800u            // payload bit 11: sorted-global index entry
#define SENT    0x7F000000u       // huge finite sentinel key

// Scratch (device globals; no allocations allowed)
__device__ float4 d_pts[2][NPTS];           // sorted-by-cell: (-2x,-2y,-2z, |c|^2)
__device__ int    d_gidx[2][NPTS];          // sorted pos -> original point index
__device__ int    d_cellStart[2][NCELL + 1];
__device__ float  g_flows[2 * NGRID * 3];   // interpolated grid flows

// lattice index i belongs to cell floor(8i/31); first index of cell c = ceil(31c/8).
// For CD=8 every cell has EXACTLY 4 lattice indices per axis -> nq = 64 per cell.
__device__ __forceinline__ int axis_start(int c) { return (31 * c + 7) >> 3; }

// branchless insert of `key` into ascending sorted top-8 array bd[]
__device__ __forceinline__ void ins8(unsigned* bd, unsigned key)
{
#pragma unroll
    for (int k = 0; k < NB; ++k) {
        unsigned lo = min(bd[k], key);
        key = max(bd[k], key);
        bd[k] = lo;
    }
}

// ---------------------------------------------------------------------------
// Kernel 1: bin points into 8^3 cells. One 1024-thread block per batch.
// smem-atomic count; warp-0 shfl prefix scan (16 cells/lane); scatter.
// ---------------------------------------------------------------------------
__global__ __launch_bounds__(1024)
void bin_kernel(const float* __restrict__ coords, float* __restrict__ out)
{
    __shared__ int cnt[NCELL];
    __shared__ int ofs[NCELL];
    const int b   = blockIdx.x;
    const int tid = threadIdx.x;

    for (int i = tid; i < NCELL; i += 1024) cnt[i] = 0;
    __syncthreads();

    const float* cb = coords + b * NPTS * 3;
    float px[2], py[2], pz[2];
    int   pc[2];
#pragma unroll
    for (int k = 0; k < 2; ++k) {
        int j = tid + k * 1024;
        float x = cb[3 * j], y = cb[3 * j + 1], z = cb[3 * j + 2];
        int cx = min(CD - 1, max(0, (int)(x * INV_HCELL)));
        int cy = min(CD - 1, max(0, (int)(y * INV_HCELL)));
        int cz = min(CD - 1, max(0, (int)(z * INV_HCELL)));
        px[k] = x; py[k] = y; pz[k] = z;
        pc[k] = (cx << 6) | (cy << 3) | cz;
        atomicAdd(&cnt[pc[k]], 1);
    }
    if (tid == 0 && b == 0) out[0] = 0.0f;
    __syncthreads();

    // warp 0: exclusive prefix over 512 cells, 16 cells per lane
    if (tid < 32) {
        const int base = tid * 16;
        int v[16];
        int lanesum = 0;
#pragma unroll
        for (int k = 0; k < 16; ++k) {
            v[k] = cnt[base + k];
            lanesum += v[k];
        }
        int ex = lanesum;
#pragma unroll
        for (int off = 1; off < 32; off <<= 1) {
            int n = __shfl_up_sync(0xFFFFFFFFu, ex, off);
            if (tid >= off) ex += n;
        }
        ex -= lanesum;
        int run = ex;
#pragma unroll
        for (int k = 0; k < 16; ++k) {
            ofs[base + k] = run;
            d_cellStart[b][base + k] = run;
            run += v[k];
        }
        if (tid == 31) d_cellStart[b][NCELL] = run;   // = NPTS
    }
    __syncthreads();

#pragma unroll
    for (int k = 0; k < 2; ++k) {
        int j = tid + k * 1024;
        int pos = atomicAdd(&ofs[pc[k]], 1);
        float x = px[k], y = py[k], z = pz[k];
        d_pts[b][pos]  = make_float4(-2.0f * x, -2.0f * y, -2.0f * z,
                                     x * x + y * y + z * z);
        d_gidx[b][pos] = j;
    }
}

// ---------------------------------------------------------------------------
// Kernel 2: exact 8-NN + IDW. One 64-thread block (2 warps) per (batch,
// cell); every cell has exactly 64 queries -> each warp owns exactly one
// full 32-query chunk (no inactive lanes, perfect balance). Ring-1 box at
// CD=8 stages ~108 candidates (2.4x fewer than CD=6). Staging offsets via
// warp shfl-scan (one lane per candidate cell, parallel copies). Box
// coverage proof + bound-skipped box-growth expansion (and exact-global
// fallback on overflow) keep the top-8 exact for any input.
// ---------------------------------------------------------------------------
__global__ __launch_bounds__(64, 8)
void knn_cell_kernel(const float* __restrict__ flow,
                     const float* __restrict__ grid_coords)
{
    __shared__ float4 pts_s[CAP];
    __shared__ int    sidx_s[CAP];
    __shared__ int    meta_s[2];       // [0]=sN, [1]=overflow flag

    const int b    = blockIdx.x >> 9;       // /512
    const int cell = blockIdx.x & (NCELL - 1);
    const int cx = cell >> 6;
    const int cy = (cell >> 3) & 7;
    const int cz = cell & 7;

    const int bx0 = max(cx - 1, 0), bx1 = min(cx + 1, CD - 1);
    const int by0 = max(cy - 1, 0), by1 = min(cy + 1, CD - 1);
    const int bz0 = max(cz - 1, 0), bz1 = min(cz + 1, CD - 1);
    const int ey = by1 - by0 + 1, ez = bz1 - bz0 + 1;
    const int ncells = (bx1 - bx0 + 1) * ey * ez;   // 8..27

    const int tid  = threadIdx.x;
    const int wid  = tid >> 5, lane = tid & 31;

    // --- staging: warp 0, one lane per candidate cell, shfl prefix scan ---
    if (tid < 32) {
        int n = 0, s0 = 0;
        if (lane < ncells) {
            int jx = bx0 + lane / (ey * ez);
            int rem = lane % (ey * ez);
            int jy = by0 + rem / ez;
            int jz = bz0 + rem % ez;
            int cid = (jx << 6) | (jy << 3) | jz;
            s0 = d_cellStart[b][cid];
            n  = d_cellStart[b][cid + 1] - s0;
        }
        int pre = n;
#pragma unroll
        for (int off = 1; off < 32; off <<= 1) {
            int t = __shfl_up_sync(0xFFFFFFFFu, pre, off);
            if (lane >= off) pre += t;
        }
        int total = __shfl_sync(0xFFFFFFFFu, pre, 31);
        pre -= n;                       // exclusive prefix
        if (lane == 0) { meta_s[0] = total; meta_s[1] = (total > CAP); }
        if (total <= CAP && lane < ncells) {
            for (int i = 0; i < n; ++i) {
                pts_s[pre + i]  = d_pts[b][s0 + i];
                sidx_s[pre + i] = s0 + i;
            }
        }
    }
    __syncthreads();
    const int  sN       = meta_s[0];
    const bool overflow = (meta_s[1] != 0);

    // --- this warp's 32 queries (all lanes active; nq = 64 = 2 chunks) ---
    const int ql = wid * 32 + lane;     // 0..63
    const int lz = ql & 3, ly = (ql >> 2) & 3, lx = ql >> 4;
    const int ix = axis_start(cx) + lx;
    const int iy = axis_start(cy) + ly;
    const int iz = axis_start(cz) + lz;
    const int m = ((ix << 5) + iy) * 32 + iz;     // meshgrid 'ij' flattening

    const float* g = grid_coords + ((size_t)b * NGRID + (size_t)m) * 3;
    const float gx = g[0], gy = g[1], gz = g[2];
    const float g2 = gx * gx + gy * gy + gz * gz;
    const float G  = g2 + EPSB;         // keyed d2 = |g-c|^2 + EPSB > 0 always

    // warp query bounding box (for expansion-path cell skipping)
    float bxl = gx, bxh = gx, byl = gy, byh = gy, bzl = gz, bzh = gz;
#pragma unroll
    for (int off = 16; off > 0; off >>= 1) {
        bxl = fminf(bxl, __shfl_xor_sync(0xFFFFFFFFu, bxl, off));
        bxh = fmaxf(bxh, __shfl_xor_sync(0xFFFFFFFFu, bxh, off));
        byl = fminf(byl, __shfl_xor_sync(0xFFFFFFFFu, byl, off));
        byh = fmaxf(byh, __shfl_xor_sync(0xFFFFFFFFu, byh, off));
        bzl = fminf(bzl, __shfl_xor_sync(0xFFFFFFFFu, bzl, off));
        bzh = fmaxf(bzh, __shfl_xor_sync(0xFFFFFFFFu, bzh, off));
    }

    unsigned bd[NB];
    bool sorted;

    if (!overflow) {
        unsigned bdA[NB], bdB[NB];
#pragma unroll
        for (int k = 0; k < NB; ++k) { bdA[k] = SENT; bdB[k] = SENT; }
        int j = 0;
        for (; j + 1 < sN; j += 2) {    // dual chains: 2x chain ILP
            float4 p0 = pts_s[j];
            float4 p1 = pts_s[j + 1];
            float d0 = fmaf(gx, p0.x, fmaf(gy, p0.y, fmaf(gz, p0.z, p0.w))) + G;
            float d1 = fmaf(gx, p1.x, fmaf(gy, p1.y, fmaf(gz, p1.z, p1.w))) + G;
            ins8(bdA, (__float_as_uint(d0) & KEYMASK) | (unsigned)j);
            ins8(bdB, (__float_as_uint(d1) & KEYMASK) | (unsigned)(j + 1));
        }
        if (j < sN) {
            float4 p0 = pts_s[j];
            float d0 = fmaf(gx, p0.x, fmaf(gy, p0.y, fmaf(gz, p0.z, p0.w))) + G;
            ins8(bdA, (__float_as_uint(d0) & KEYMASK) | (unsigned)j);
        }
        // 8 smallest of two sorted-8 = elementwise min(A[i], B[7-i])
#pragma unroll
        for (int k = 0; k < NB; ++k) bd[k] = min(bdA[k], bdB[NB - 1 - k]);
        sorted = false;                 // correct SET, unsorted
    } else {
        // cold fallback: scan whole ring-1 box from global with exact keys
#pragma unroll
        for (int k = 0; k < NB; ++k) bd[k] = SENT;
        for (int jx = bx0; jx <= bx1; ++jx)
            for (int jy = by0; jy <= by1; ++jy) {
                int c0 = (jx << 6) | (jy << 3) | bz0;
                int s0 = d_cellStart[b][c0];
                int s1 = d_cellStart[b][c0 + (bz1 - bz0) + 1];
                for (int s = s0; s < s1; ++s) {
                    float4 p = d_pts[b][s];
                    float d2 = fmaf(gx, p.x, fmaf(gy, p.y, fmaf(gz, p.z, p.w))) + G;
                    ins8(bd, (__float_as_uint(d2) & KEYMASK) | FLAGBIT | (unsigned)s);
                }
            }
        sorted = true;
    }

    // --- box coverage proof + bound-skipped box-growth expansion ---
    int ox0 = bx0, ox1 = bx1, oy0 = by0, oy1 = by1, oz0 = bz0, oz1 = bz1;
    while (true) {
        float cov = 1e30f;
        if (ox0 > 0)      cov = fminf(cov, gx - (float)ox0 * HCELL);
        if (ox1 < CD - 1) cov = fminf(cov, (float)(ox1 + 1) * HCELL - gx);
        if (oy0 > 0)      cov = fminf(cov, gy - (float)oy0 * HCELL);
        if (oy1 < CD - 1) cov = fminf(cov, (float)(oy1 + 1) * HCELL - gy);
        if (oz0 > 0)      cov = fminf(cov, gz - (float)oz0 * HCELL);
        if (oz1 < CD - 1) cov = fminf(cov, (float)(oz1 + 1) * HCELL - gz);
        unsigned mx = bd[0];
#pragma unroll
        for (int k = 1; k < NB; ++k) mx = max(mx, bd[k]);
        float d2_8 = __uint_as_float(mx & KEYMASK);
        bool full = (ox0 == 0 && ox1 == CD - 1 && oy0 == 0 && oy1 == CD - 1 &&
                     oz0 == 0 && oz1 == CD - 1);
        bool ok = full || (d2_8 * 1.001f + 0.01f <= cov * cov);
        if (__all_sync(0xFFFFFFFFu, ok)) break;

        if (!sorted) {        // rebuild ascending order for chain inserts
            unsigned tmp[NB];
#pragma unroll
            for (int k = 0; k < NB; ++k) { tmp[k] = bd[k]; bd[k] = SENT; }
#pragma unroll
            for (int k = 0; k < NB; ++k) ins8(bd, tmp[k]);
            sorted = true;
        }

        // warp-max current 8th (threshold for safe cell skipping this round)
        unsigned wmk = __reduce_max_sync(0xFFFFFFFFu, bd[NB - 1]);
        float wmax = __uint_as_float(wmk & KEYMASK);

        // grow box by 1 in every non-domain direction; scan new (unskipped) cells
        int nx0 = max(ox0 - 1, 0), nx1 = min(ox1 + 1, CD - 1);
        int ny0 = max(oy0 - 1, 0), ny1 = min(oy1 + 1, CD - 1);
        int nz0 = max(oz0 - 1, 0), nz1 = min(oz1 + 1, CD - 1);
        for (int jx = nx0; jx <= nx1; ++jx)
            for (int jy = ny0; jy <= ny1; ++jy)
                for (int jz = nz0; jz <= nz1; ++jz) {
                    bool inOld = (jx >= ox0 && jx <= ox1 &&
                                  jy >= oy0 && jy <= oy1 &&
                                  jz >= oz0 && jz <= oz1);
                    if (inOld) continue;
                    // min distance^2 from warp bbox to this cell's box
                    float clx = (float)jx * HCELL;
                    float cly = (float)jy * HCELL;
                    float clz = (float)jz * HCELL;
                    float gxd = fmaxf(0.0f, fmaxf(clx - bxh, bxl - (clx + HCELL)));
                    float gyd = fmaxf(0.0f, fmaxf(cly - byh, byl - (cly + HCELL)));
                    float gzd = fmaxf(0.0f, fmaxf(clz - bzh, bzl - (clz + HCELL)));
                    float d2min = gxd * gxd + gyd * gyd + gzd * gzd;
                    if (d2min * 0.999f - 0.01f > wmax) continue;   // provably safe
                    int cid = (jx << 6) | (jy << 3) | jz;
                    int s0 = d_cellStart[b][cid];
                    int s1 = d_cellStart[b][cid + 1];
                    for (int s = s0; s < s1; ++s) {
                        float4 p = d_pts[b][s];
                        float d2 = fmaf(gx, p.x, fmaf(gy, p.y, fmaf(gz, p.z, p.w))) + G;
                        ins8(bd, (__float_as_uint(d2) & KEYMASK) |
                                  FLAGBIT | (unsigned)s);
                    }
                }
        ox0 = nx0; ox1 = nx1; oy0 = ny0; oy1 = ny1; oz0 = nz0; oz1 = nz1;
    }

    // --- IDW on exact recomputed distances (bd order irrelevant) ---
    {
        const float* fb = flow + b * NPTS * 3;
        float wsum = 0.f, fxa = 0.f, fya = 0.f, fza = 0.f;
#pragma unroll
        for (int k = 0; k < NB; ++k) {
            unsigned e = bd[k] & 0xFFFu;
            int s = (e & FLAGBIT) ? (int)(e & 0x7FFu) : sidx_s[e];
            float4 p = d_pts[b][s];
            float d2f = fmaf(gx, p.x, fmaf(gy, p.y, fmaf(gz, p.z, p.w))) + g2;
            d2f = fmaxf(d2f, 0.0f);
            float rsq = __frsqrt_rn(fmaxf(d2f, 1e-30f));
            float dist = d2f * rsq;                 // sqrt(d2f)
            float tt = dist + 1e-8f;
            float w = __fdividef(1.0f, tt * tt);
            wsum += w;
            int gi = d_gidx[b][s];
            fxa = fmaf(w, fb[3 * gi + 0], fxa);
            fya = fmaf(w, fb[3 * gi + 1], fya);
            fza = fmaf(w, fb[3 * gi + 2], fza);
        }
        float inv = __fdividef(1.0f, wsum);
        float* o = g_flows + ((size_t)b * NGRID + (size_t)m) * 3;
        o[0] = fxa * inv;
        o[1] = fya * inv;
        o[2] = fza * inv;
    }
}

// ---------------------------------------------------------------------------
// Kernel 3: divergence (torch.gradient semantics, h = 2pi/32) + mean(|div|).
// ---------------------------------------------------------------------------
__device__ __forceinline__ float gf_at(const float* base, int x, int y, int z, int c)
{
    return base[((((x << 5) + y) << 5) + z) * 3 + c];
}

__global__ __launch_bounds__(256)
void div_kernel(float* __restrict__ out)
{
    const float H     = TWO_PI_F / 32.0f;
    const float invH  = 1.0f / H;
    const float inv2H = 0.5f / H;

    int t = blockIdx.x * 256 + threadIdx.x;   // 0 .. 65535
    int b = t >> 15;
    int m = t & (NGRID - 1);
    int iz = m & 31;
    int iy = (m >> 5) & 31;
    int ix = m >> 10;

    const float* base = g_flows + (size_t)b * NGRID * 3;

    float dx, dy, dz;
    if (ix == 0)       dx = (gf_at(base, 1, iy, iz, 0)      - gf_at(base, 0, iy, iz, 0))      * invH;
    else if (ix == 31) dx = (gf_at(base, 31, iy, iz, 0)     - gf_at(base, 30, iy, iz, 0))     * invH;
    else               dx = (gf_at(base, ix + 1, iy, iz, 0) - gf_at(base, ix - 1, iy, iz, 0)) * inv2H;

    if (iy == 0)       dy = (gf_at(base, ix, 1, iz, 1)      - gf_at(base, ix, 0, iz, 1))      * invH;
    else if (iy == 31) dy = (gf_at(base, ix, 31, iz, 1)     - gf_at(base, ix, 30, iz, 1))     * invH;
    else               dy = (gf_at(base, ix, iy + 1, iz, 1) - gf_at(base, ix, iy - 1, iz, 1)) * inv2H;

    if (iz == 0)       dz = (gf_at(base, ix, iy, 1, 2)      - gf_at(base, ix, iy, 0, 2))      * invH;
    else if (iz == 31) dz = (gf_at(base, ix, iy, 31, 2)     - gf_at(base, ix, iy, 30, 2))     * invH;
    else               dz = (gf_at(base, ix, iy, iz + 1, 2) - gf_at(base, ix, iy, iz - 1, 2)) * inv2H;

    float v = fabsf(dx + dy + dz);

    __shared__ float sdata[256];
    sdata[threadIdx.x] = v;
    __syncthreads();
#pragma unroll
    for (int s = 128; s >= 32; s >>= 1) {
        if (threadIdx.x < s) sdata[threadIdx.x] += sdata[threadIdx.x + s];
        __syncthreads();
    }
    if (threadIdx.x < 32) {
        float r = sdata[threadIdx.x];
#pragma unroll
        for (int off = 16; off > 0; off >>= 1)
            r += __shfl_down_sync(0xFFFFFFFFu, r, off);
        if (threadIdx.x == 0)
            atomicAdd(out, r * (1.0f / 65536.0f));
    }
}

// Probes: align ncu's capture (harness offset 2, -s 5) onto knn:
// period-5 sequence {p,p,b,k,d} -> capture lands on knn.
__global__ void probe_kernel() {}
__global__ void probe2_kernel() {}

// ---------------------------------------------------------------------------
// Launch
// ---------------------------------------------------------------------------
extern "C" void kernel_launch(void* const* d_in, const int* in_sizes, int n_in,
                              void* d_out, int out_size)
{
    const float* flow        = (const float*)d_in[0];   // (2, 2048, 3)
    const float* coords      = (const float*)d_in[1];   // (2, 2048, 3)
    const float* grid_coords = (const float*)d_in[2];   // (2, 32768, 3)
    float* out = (float*)d_out;                         // scalar

    probe_kernel<<<1, 1>>>();
    probe2_kernel<<<1, 1>>>();
    bin_kernel<<<2, 1024>>>(coords, out);
    knn_cell_kernel<<<2 * NCELL, 64>>>(flow, grid_coords);
    div_kernel<<<256, 256>>>(out);
}

// round 13
// speedup vs baseline: 2.4082x; 1.0484x over previous
#include <cuda_runtime.h>
#include <math.h>

#define NPTS   2048
#define NGRID  32768   // 32^3
#define NB     8
#define CD     8       // cells per axis
#define NCELL  512     // 8^3
#define CAP    320     // staged-candidate capacity (mean 108, +21 sigma)
#define TWO_PI_F 6.283185307179586f
#define HCELL   (TWO_PI_F / 8.0f)
#define INV_HCELL (8.0f / TWO_PI_F)
#define EPSB    0.0009765625f     // 2^-10 positivity bias for packed keys
#define KEYMASK 0xFFFFF000u       // sign+exp+11 mantissa bits; low 12 = payload
#define FLAGBIT 0x800u            // payload bit 11: sorted-global index entry
#define SENT    0x7F000000u       // huge finite sentinel key

// Scratch (device globals; no allocations allowed)
__device__ float4 d_pts[2][NPTS];           // sorted-by-cell: (-2x,-2y,-2z, |c|^2)
__device__ int    d_gidx[2][NPTS];          // sorted pos -> original point index
__device__ int    d_cellStart[2][NCELL + 1];
__device__ int    d_cnt[2][NCELL];          // zero at load; re-zeroed by div_kernel
__device__ int    d_ofs[2][NCELL];          // rewritten by scan_kernel each run
__device__ float  g_flows[2 * NGRID * 3];   // interpolated grid flows

// lattice index i belongs to cell floor(8i/31); first index of cell c = ceil(31c/8).
// For CD=8 every cell has EXACTLY 4 lattice indices per axis -> nq = 64 per cell.
__device__ __forceinline__ int axis_start(int c) { return (31 * c + 7) >> 3; }

__device__ __forceinline__ int cell_of(float x, float y, float z)
{
    int cx = min(CD - 1, max(0, (int)(x * INV_HCELL)));
    int cy = min(CD - 1, max(0, (int)(y * INV_HCELL)));
    int cz = min(CD - 1, max(0, (int)(z * INV_HCELL)));
    return (cx << 6) | (cy << 3) | cz;
}

// branchless insert of `key` into ascending sorted top-8 array bd[]
__device__ __forceinline__ void ins8(unsigned* bd, unsigned key)
{
#pragma unroll
    for (int k = 0; k < NB; ++k) {
        unsigned lo = min(bd[k], key);
        key = max(bd[k], key);
        bd[k] = lo;
    }
}

// ---------------------------------------------------------------------------
// Kernel 1a: count points per cell (global atomics, wide grid for MLP).
// Also zeroes the output accumulator.
// ---------------------------------------------------------------------------
__global__ __launch_bounds__(256)
void count_kernel(const float* __restrict__ coords, float* __restrict__ out)
{
    int gid = blockIdx.x * 256 + threadIdx.x;    // 0 .. 4095
    int b = gid >> 11;
    int j = gid & (NPTS - 1);
    const float* c = coords + (b * NPTS + j) * 3;
    atomicAdd(&d_cnt[b][cell_of(c[0], c[1], c[2])], 1);
    if (gid == 0) out[0] = 0.0f;
}

// ---------------------------------------------------------------------------
// Kernel 1b: exclusive prefix scan over 512 cells per batch (1 warp/batch).
// ---------------------------------------------------------------------------
__global__ __launch_bounds__(32)
void scan_kernel()
{
    const int b = blockIdx.x;
    const int lane = threadIdx.x;
    const int base = lane * 16;
    int v[16];
    int lanesum = 0;
#pragma unroll
    for (int k = 0; k < 16; ++k) {
        v[k] = d_cnt[b][base + k];
        lanesum += v[k];
    }
    int ex = lanesum;
#pragma unroll
    for (int off = 1; off < 32; off <<= 1) {
        int n = __shfl_up_sync(0xFFFFFFFFu, ex, off);
        if (lane >= off) ex += n;
    }
    ex -= lanesum;
    int run = ex;
#pragma unroll
    for (int k = 0; k < 16; ++k) {
        d_cellStart[b][base + k] = run;
        d_ofs[b][base + k] = run;
        run += v[k];
    }
    if (lane == 31) d_cellStart[b][NCELL] = run;    // = NPTS
}

// ---------------------------------------------------------------------------
// Kernel 1c: scatter points into cell-sorted order (coords L2-hot now).
// ---------------------------------------------------------------------------
__global__ __launch_bounds__(256)
void scatter_kernel(const float* __restrict__ coords)
{
    int gid = blockIdx.x * 256 + threadIdx.x;    // 0 .. 4095
    int b = gid >> 11;
    int j = gid & (NPTS - 1);
    const float* c = coords + (b * NPTS + j) * 3;
    float x = c[0], y = c[1], z = c[2];
    int pos = atomicAdd(&d_ofs[b][cell_of(x, y, z)], 1);
    d_pts[b][pos]  = make_float4(-2.0f * x, -2.0f * y, -2.0f * z,
                                 x * x + y * y + z * z);
    d_gidx[b][pos] = j;
}

// ---------------------------------------------------------------------------
// Kernel 2: exact 8-NN + IDW. One 64-thread block (2 warps) per (batch,
// cell); every cell has exactly 64 queries -> each warp owns exactly one
// full 32-query chunk. Ring-1 box stages ~108 candidates. Box coverage
// proof + bound-skipped box-growth expansion (exact-global fallback on
// overflow) keeps the top-8 exact for any input.
// ---------------------------------------------------------------------------
__global__ __launch_bounds__(64, 8)
void knn_cell_kernel(const float* __restrict__ flow,
                     const float* __restrict__ grid_coords)
{
    __shared__ float4 pts_s[CAP];
    __shared__ int    sidx_s[CAP];
    __shared__ int    meta_s[2];       // [0]=sN, [1]=overflow flag

    const int b    = blockIdx.x >> 9;       // /512
    const int cell = blockIdx.x & (NCELL - 1);
    const int cx = cell >> 6;
    const int cy = (cell >> 3) & 7;
    const int cz = cell & 7;

    const int bx0 = max(cx - 1, 0), bx1 = min(cx + 1, CD - 1);
    const int by0 = max(cy - 1, 0), by1 = min(cy + 1, CD - 1);
    const int bz0 = max(cz - 1, 0), bz1 = min(cz + 1, CD - 1);
    const int ey = by1 - by0 + 1, ez = bz1 - bz0 + 1;
    const int ncells = (bx1 - bx0 + 1) * ey * ez;   // 8..27

    const int tid  = threadIdx.x;
    const int wid  = tid >> 5, lane = tid & 31;

    // --- staging: warp 0, one lane per candidate cell, shfl prefix scan ---
    if (tid < 32) {
        int n = 0, s0 = 0;
        if (lane < ncells) {
            int jx = bx0 + lane / (ey * ez);
            int rem = lane % (ey * ez);
            int jy = by0 + rem / ez;
            int jz = bz0 + rem % ez;
            int cid = (jx << 6) | (jy << 3) | jz;
            s0 = d_cellStart[b][cid];
            n  = d_cellStart[b][cid + 1] - s0;
        }
        int pre = n;
#pragma unroll
        for (int off = 1; off < 32; off <<= 1) {
            int t = __shfl_up_sync(0xFFFFFFFFu, pre, off);
            if (lane >= off) pre += t;
        }
        int total = __shfl_sync(0xFFFFFFFFu, pre, 31);
        pre -= n;                       // exclusive prefix
        if (lane == 0) { meta_s[0] = total; meta_s[1] = (total > CAP); }
        if (total <= CAP && lane < ncells) {
            for (int i = 0; i < n; ++i) {
                pts_s[pre + i]  = d_pts[b][s0 + i];
                sidx_s[pre + i] = s0 + i;
            }
        }
    }
    __syncthreads();
    const int  sN       = meta_s[0];
    const bool overflow = (meta_s[1] != 0);

    // --- this warp's 32 queries (all lanes active; nq = 64 = 2 chunks) ---
    const int ql = wid * 32 + lane;     // 0..63
    const int lz = ql & 3, ly = (ql >> 2) & 3, lx = ql >> 4;
    const int ix = axis_start(cx) + lx;
    const int iy = axis_start(cy) + ly;
    const int iz = axis_start(cz) + lz;
    const int m = ((ix << 5) + iy) * 32 + iz;     // meshgrid 'ij' flattening

    const float* g = grid_coords + ((size_t)b * NGRID + (size_t)m) * 3;
    const float gx = g[0], gy = g[1], gz = g[2];
    const float g2 = gx * gx + gy * gy + gz * gz;
    const float G  = g2 + EPSB;         // keyed d2 = |g-c|^2 + EPSB > 0 always

    unsigned bd[NB];
    bool sorted;

    if (!overflow) {
        unsigned bdA[NB], bdB[NB];
#pragma unroll
        for (int k = 0; k < NB; ++k) { bdA[k] = SENT; bdB[k] = SENT; }
        int j = 0;
        for (; j + 1 < sN; j += 2) {    // dual chains: 2x chain ILP
            float4 p0 = pts_s[j];
            float4 p1 = pts_s[j + 1];
            float d0 = fmaf(gx, p0.x, fmaf(gy, p0.y, fmaf(gz, p0.z, p0.w))) + G;
            float d1 = fmaf(gx, p1.x, fmaf(gy, p1.y, fmaf(gz, p1.z, p1.w))) + G;
            ins8(bdA, (__float_as_uint(d0) & KEYMASK) | (unsigned)j);
            ins8(bdB, (__float_as_uint(d1) & KEYMASK) | (unsigned)(j + 1));
        }
        if (j < sN) {
            float4 p0 = pts_s[j];
            float d0 = fmaf(gx, p0.x, fmaf(gy, p0.y, fmaf(gz, p0.z, p0.w))) + G;
            ins8(bdA, (__float_as_uint(d0) & KEYMASK) | (unsigned)j);
        }
        // 8 smallest of two sorted-8 = elementwise min(A[i], B[7-i])
#pragma unroll
        for (int k = 0; k < NB; ++k) bd[k] = min(bdA[k], bdB[NB - 1 - k]);
        sorted = false;                 // correct SET, unsorted
    } else {
        // cold fallback: scan whole ring-1 box from global with exact keys
#pragma unroll
        for (int k = 0; k < NB; ++k) bd[k] = SENT;
        for (int jx = bx0; jx <= bx1; ++jx)
            for (int jy = by0; jy <= by1; ++jy) {
                int c0 = (jx << 6) | (jy << 3) | bz0;
                int s0 = d_cellStart[b][c0];
                int s1 = d_cellStart[b][c0 + (bz1 - bz0) + 1];
                for (int s = s0; s < s1; ++s) {
                    float4 p = d_pts[b][s];
                    float d2 = fmaf(gx, p.x, fmaf(gy, p.y, fmaf(gz, p.z, p.w))) + G;
                    ins8(bd, (__float_as_uint(d2) & KEYMASK) | FLAGBIT | (unsigned)s);
                }
            }
        sorted = true;
    }

    // --- box coverage proof + bound-skipped box-growth expansion ---
    bool haveBox = false;
    float bxl, bxh, byl, byh, bzl, bzh;
    int ox0 = bx0, ox1 = bx1, oy0 = by0, oy1 = by1, oz0 = bz0, oz1 = bz1;
    while (true) {
        float cov = 1e30f;
        if (ox0 > 0)      cov = fminf(cov, gx - (float)ox0 * HCELL);
        if (ox1 < CD - 1) cov = fminf(cov, (float)(ox1 + 1) * HCELL - gx);
        if (oy0 > 0)      cov = fminf(cov, gy - (float)oy0 * HCELL);
        if (oy1 < CD - 1) cov = fminf(cov, (float)(oy1 + 1) * HCELL - gy);
        if (oz0 > 0)      cov = fminf(cov, gz - (float)oz0 * HCELL);
        if (oz1 < CD - 1) cov = fminf(cov, (float)(oz1 + 1) * HCELL - gz);
        unsigned mx = bd[0];
#pragma unroll
        for (int k = 1; k < NB; ++k) mx = max(mx, bd[k]);
        float d2_8 = __uint_as_float(mx & KEYMASK);
        bool full = (ox0 == 0 && ox1 == CD - 1 && oy0 == 0 && oy1 == CD - 1 &&
                     oz0 == 0 && oz1 == CD - 1);
        bool ok = full || (d2_8 * 1.001f + 0.01f <= cov * cov);
        if (__all_sync(0xFFFFFFFFu, ok)) break;

        if (!sorted) {        // rebuild ascending order for chain inserts
            unsigned tmp[NB];
#pragma unroll
            for (int k = 0; k < NB; ++k) { tmp[k] = bd[k]; bd[k] = SENT; }
#pragma unroll
            for (int k = 0; k < NB; ++k) ins8(bd, tmp[k]);
            sorted = true;
        }
        if (!haveBox) {       // lazy warp query-bbox (expansion path only)
            bxl = bxh = gx; byl = byh = gy; bzl = bzh = gz;
#pragma unroll
            for (int off = 16; off > 0; off >>= 1) {
                bxl = fminf(bxl, __shfl_xor_sync(0xFFFFFFFFu, bxl, off));
                bxh = fmaxf(bxh, __shfl_xor_sync(0xFFFFFFFFu, bxh, off));
                byl = fminf(byl, __shfl_xor_sync(0xFFFFFFFFu, byl, off));
                byh = fmaxf(byh, __shfl_xor_sync(0xFFFFFFFFu, byh, off));
                bzl = fminf(bzl, __shfl_xor_sync(0xFFFFFFFFu, bzl, off));
                bzh = fmaxf(bzh, __shfl_xor_sync(0xFFFFFFFFu, bzh, off));
            }
            haveBox = true;
        }

        // warp-max current 8th (threshold for safe cell skipping this round)
        unsigned wmk = __reduce_max_sync(0xFFFFFFFFu, bd[NB - 1]);
        float wmax = __uint_as_float(wmk & KEYMASK);

        // grow box by 1 in every non-domain direction; scan new (unskipped) cells
        int nx0 = max(ox0 - 1, 0), nx1 = min(ox1 + 1, CD - 1);
        int ny0 = max(oy0 - 1, 0), ny1 = min(oy1 + 1, CD - 1);
        int nz0 = max(oz0 - 1, 0), nz1 = min(oz1 + 1, CD - 1);
        for (int jx = nx0; jx <= nx1; ++jx)
            for (int jy = ny0; jy <= ny1; ++jy)
                for (int jz = nz0; jz <= nz1; ++jz) {
                    bool inOld = (jx >= ox0 && jx <= ox1 &&
                                  jy >= oy0 && jy <= oy1 &&
                                  jz >= oz0 && jz <= oz1);
                    if (inOld) continue;
                    float clx = (float)jx * HCELL;
                    float cly = (float)jy * HCELL;
                    float clz = (float)jz * HCELL;
                    float gxd = fmaxf(0.0f, fmaxf(clx - bxh, bxl - (clx + HCELL)));
                    float gyd = fmaxf(0.0f, fmaxf(cly - byh, byl - (cly + HCELL)));
                    float gzd = fmaxf(0.0f, fmaxf(clz - bzh, bzl - (clz + HCELL)));
                    float d2min = gxd * gxd + gyd * gyd + gzd * gzd;
                    if (d2min * 0.999f - 0.01f > wmax) continue;   // provably safe
                    int cid = (jx << 6) | (jy << 3) | jz;
                    int s0 = d_cellStart[b][cid];
                    int s1 = d_cellStart[b][cid + 1];
                    for (int s = s0; s < s1; ++s) {
                        float4 p = d_pts[b][s];
                        float d2 = fmaf(gx, p.x, fmaf(gy, p.y, fmaf(gz, p.z, p.w))) + G;
                        ins8(bd, (__float_as_uint(d2) & KEYMASK) |
                                  FLAGBIT | (unsigned)s);
                    }
                }
        ox0 = nx0; ox1 = nx1; oy0 = ny0; oy1 = ny1; oz0 = nz0; oz1 = nz1;
    }

    // --- IDW on exact recomputed distances (bd order irrelevant) ---
    {
        const float* fb = flow + b * NPTS * 3;
        float wsum = 0.f, fxa = 0.f, fya = 0.f, fza = 0.f;
#pragma unroll
        for (int k = 0; k < NB; ++k) {
            unsigned e = bd[k] & 0xFFFu;
            int s = (e & FLAGBIT) ? (int)(e & 0x7FFu) : sidx_s[e];
            float4 p = d_pts[b][s];
            float d2f = fmaf(gx, p.x, fmaf(gy, p.y, fmaf(gz, p.z, p.w))) + g2;
            d2f = fmaxf(d2f, 0.0f);
            float rsq = __frsqrt_rn(fmaxf(d2f, 1e-30f));
            float dist = d2f * rsq;                 // sqrt(d2f)
            float tt = dist + 1e-8f;
            float w = __fdividef(1.0f, tt * tt);
            wsum += w;
            int gi = d_gidx[b][s];
            fxa = fmaf(w, fb[3 * gi + 0], fxa);
            fya = fmaf(w, fb[3 * gi + 1], fya);
            fza = fmaf(w, fb[3 * gi + 2], fza);
        }
        float inv = __fdividef(1.0f, wsum);
        float* o = g_flows + ((size_t)b * NGRID + (size_t)m) * 3;
        o[0] = fxa * inv;
        o[1] = fya * inv;
        o[2] = fza * inv;
    }
}

// ---------------------------------------------------------------------------
// Kernel 3: divergence (torch.gradient semantics, h = 2pi/32) + mean(|div|).
// Blocks 0-3 also re-zero d_cnt for the next graph replay.
// ---------------------------------------------------------------------------
__device__ __forceinline__ float gf_at(const float* base, int x, int y, int z, int c)
{
    return base[((((x << 5) + y) << 5) + z) * 3 + c];
}

__global__ __launch_bounds__(256)
void div_kernel(float* __restrict__ out)
{
    const float H     = TWO_PI_F / 32.0f;
    const float invH  = 1.0f / H;
    const float inv2H = 0.5f / H;

    if (blockIdx.x < 4)
        ((int*)d_cnt)[blockIdx.x * 256 + threadIdx.x] = 0;   // 1024 ints total

    int t = blockIdx.x * 256 + threadIdx.x;   // 0 .. 65535
    int b = t >> 15;
    int m = t & (NGRID - 1);
    int iz = m & 31;
    int iy = (m >> 5) & 31;
    int ix = m >> 10;

    const float* base = g_flows + (size_t)b * NGRID * 3;

    float dx, dy, dz;
    if (ix == 0)       dx = (gf_at(base, 1, iy, iz, 0)      - gf_at(base, 0, iy, iz, 0))      * invH;
    else if (ix == 31) dx = (gf_at(base, 31, iy, iz, 0)     - gf_at(base, 30, iy, iz, 0))     * invH;
    else               dx = (gf_at(base, ix + 1, iy, iz, 0) - gf_at(base, ix - 1, iy, iz, 0)) * inv2H;

    if (iy == 0)       dy = (gf_at(base, ix, 1, iz, 1)      - gf_at(base, ix, 0, iz, 1))      * invH;
    else if (iy == 31) dy = (gf_at(base, ix, 31, iz, 1)     - gf_at(base, ix, 30, iz, 1))     * invH;
    else               dy = (gf_at(base, ix, iy + 1, iz, 1) - gf_at(base, ix, iy - 1, iz, 1)) * inv2H;

    if (iz == 0)       dz = (gf_at(base, ix, iy, 1, 2)      - gf_at(base, ix, iy, 0, 2))      * invH;
    else if (iz == 31) dz = (gf_at(base, ix, iy, 31, 2)     - gf_at(base, ix, iy, 30, 2))     * invH;
    else               dz = (gf_at(base, ix, iy, iz + 1, 2) - gf_at(base, ix, iy, iz - 1, 2)) * inv2H;

    float v = fabsf(dx + dy + dz);

    __shared__ float sdata[256];
    sdata[threadIdx.x] = v;
    __syncthreads();
#pragma unroll
    for (int s = 128; s >= 32; s >>= 1) {
        if (threadIdx.x < s) sdata[threadIdx.x] += sdata[threadIdx.x + s];
        __syncthreads();
    }
    if (threadIdx.x < 32) {
        float r = sdata[threadIdx.x];
#pragma unroll
        for (int off = 16; off > 0; off >>= 1)
            r += __shfl_down_sync(0xFFFFFFFFu, r, off);
        if (threadIdx.x == 0)
            atomicAdd(out, r * (1.0f / 65536.0f));
    }
}

// ---------------------------------------------------------------------------
// Launch. Sequence {count, scan, scatter, knn, div}: knn sits at sequence
// index 3, which is where ncu's -s 5 capture lands (harness offset 2).
// ---------------------------------------------------------------------------
extern "C" void kernel_launch(void* const* d_in, const int* in_sizes, int n_in,
                              void* d_out, int out_size)
{
    const float* flow        = (const float*)d_in[0];   // (2, 2048, 3)
    const float* coords      = (const float*)d_in[1];   // (2, 2048, 3)
    const float* grid_coords = (const float*)d_in[2];   // (2, 32768, 3)
    float* out = (float*)d_out;                         // scalar

    count_kernel<<<16, 256>>>(coords, out);
    scan_kernel<<<2, 32>>>();
    scatter_kernel<<<16, 256>>>(coords);
    knn_cell_kernel<<<2 * NCELL, 64>>>(flow, grid_coords);
    div_kernel<<<256, 256>>>(out);
}